// round 2
// baseline (speedup 1.0000x reference)
#include <cuda_runtime.h>

#define NN  50000
#define ER  1600000
#define EMB 32
#define HID 128

// ---------------- device scratch (static allocation, no cudaMalloc) ----------------
__device__ int   g_deg[NN];
__device__ float g_dinv[NN];
__device__ int   g_rowstart[NN];
__device__ int   g_cursor[NN];
__device__ int   g_col[ER];
__device__ int   g_total;
__device__ float g_aggemb[NN * EMB];     //  6.4 MB
__device__ float g_h1[NN * HID];         // 25.6 MB
__device__ float g_agg2[NN * HID];       // 25.6 MB

// ---------------- 1) init: deg = 1 (self loop), reset bump counter ----------------
__global__ void k_init() {
    int i = blockIdx.x * 256 + threadIdx.x;
    if (i < NN) g_deg[i] = 1;
    if (i == 0) g_total = 0;
}

// ---------------- 2) degree histogram over dst (edge_index is int32 on device) ----------------
__global__ void k_deg(const int* __restrict__ ei) {
    int e = blockIdx.x * 256 + threadIdx.x;
    if (e < ER) atomicAdd(&g_deg[ei[ER + e]], 1);
}

// ---------------- 3) dinv + CSR row allocation (warp-aggregated bump) ----------------
__global__ void k_dinv_alloc() {
    int i    = blockIdx.x * 256 + threadIdx.x;
    int lane = threadIdx.x & 31;
    int cnt  = 0;
    if (i < NN) {
        int d = g_deg[i];
        g_dinv[i] = rsqrtf((float)d);
        cnt = d - 1;                       // raw in-edges (self loop handled inline)
    }
    // warp inclusive scan of cnt
    int incl = cnt;
#pragma unroll
    for (int off = 1; off < 32; off <<= 1) {
        int t = __shfl_up_sync(0xffffffffu, incl, off);
        if (lane >= off) incl += t;
    }
    int total = __shfl_sync(0xffffffffu, incl, 31);
    int base  = 0;
    if (lane == 31) base = atomicAdd(&g_total, total);
    base = __shfl_sync(0xffffffffu, base, 31);
    if (i < NN) {
        int start = base + incl - cnt;
        g_rowstart[i] = start;
        g_cursor[i]   = start;
    }
}

// ---------------- 4) scatter edges into CSR buckets ----------------
__global__ void k_scatter(const int* __restrict__ ei) {
    int e = blockIdx.x * 256 + threadIdx.x;
    if (e < ER) {
        int s = ei[e];
        int d = ei[ER + e];
        int pos = atomicAdd(&g_cursor[d], 1);
        g_col[pos] = s;
    }
}

// ---------------- 5) aggregate embeddings (32-dim, warp per node) ----------------
__global__ void k_agg_emb(const float* __restrict__ emb) {
    int w    = (blockIdx.x * 256 + threadIdx.x) >> 5;
    int lane = threadIdx.x & 31;
    if (w >= NN) return;
    float di  = g_dinv[w];
    float acc = emb[w * EMB + lane] * di * di;   // self loop
    int start = g_rowstart[w];
    int cnt   = g_deg[w] - 1;
    for (int e = 0; e < cnt; e++) {
        int   s  = g_col[start + e];
        float ns = g_dinv[s] * di;
        acc += emb[s * EMB + lane] * ns;
    }
    g_aggemb[w * EMB + lane] = acc;
}

// ---------------- 6) GEMM1: h1 = relu(aggemb @ W1 + b1)  [50000 x 32 x 128] ----------------
__global__ void k_gemm1(const float* __restrict__ W1, const float* __restrict__ b1) {
    __shared__ float Ws[EMB * HID];   // 16 KB
    __shared__ float bs[HID];
    __shared__ float As[16 * EMB];    //  2 KB
    for (int idx = threadIdx.x; idx < EMB * HID; idx += 256) Ws[idx] = W1[idx];
    if (threadIdx.x < HID) bs[threadIdx.x] = b1[threadIdx.x];

    const int NT   = NN / 16;                 // 3125 (exact)
    int tcol = (threadIdx.x & 31) * 4;        // 0..124
    int trow = (threadIdx.x >> 5) * 2;        // 0..14

    for (int t = blockIdx.x; t < NT; t += gridDim.x) {
        int row0 = t * 16;
        __syncthreads();
        for (int idx = threadIdx.x; idx < 16 * EMB; idx += 256)
            As[idx] = g_aggemb[row0 * EMB + idx];
        __syncthreads();

        float acc[2][4];
#pragma unroll
        for (int r = 0; r < 2; r++) {
            acc[r][0] = bs[tcol]; acc[r][1] = bs[tcol + 1];
            acc[r][2] = bs[tcol + 2]; acc[r][3] = bs[tcol + 3];
        }
#pragma unroll
        for (int k = 0; k < EMB; k++) {
            float4 w4 = *reinterpret_cast<const float4*>(&Ws[k * HID + tcol]);
            float a0 = As[trow * EMB + k];
            float a1 = As[(trow + 1) * EMB + k];
            acc[0][0] += a0 * w4.x; acc[0][1] += a0 * w4.y;
            acc[0][2] += a0 * w4.z; acc[0][3] += a0 * w4.w;
            acc[1][0] += a1 * w4.x; acc[1][1] += a1 * w4.y;
            acc[1][2] += a1 * w4.z; acc[1][3] += a1 * w4.w;
        }
#pragma unroll
        for (int r = 0; r < 2; r++) {
            float4 o;
            o.x = fmaxf(acc[r][0], 0.f); o.y = fmaxf(acc[r][1], 0.f);
            o.z = fmaxf(acc[r][2], 0.f); o.w = fmaxf(acc[r][3], 0.f);
            *reinterpret_cast<float4*>(&g_h1[(row0 + trow + r) * HID + tcol]) = o;
        }
    }
}

// ---------------- 7) aggregate h1 (128-dim, warp per node, float4) ----------------
__global__ void k_agg_h1() {
    int w    = (blockIdx.x * 256 + threadIdx.x) >> 5;
    int lane = threadIdx.x & 31;
    if (w >= NN) return;
    float di = g_dinv[w];
    const float4* hv = reinterpret_cast<const float4*>(g_h1);
    float4 v  = hv[w * 32 + lane];
    float  sw = di * di;
    float4 acc = make_float4(v.x * sw, v.y * sw, v.z * sw, v.w * sw);
    int start = g_rowstart[w];
    int cnt   = g_deg[w] - 1;
    for (int e = 0; e < cnt; e++) {
        int   s  = g_col[start + e];
        float ns = g_dinv[s] * di;
        float4 u = hv[s * 32 + lane];
        acc.x += u.x * ns; acc.y += u.y * ns;
        acc.z += u.z * ns; acc.w += u.w * ns;
    }
    reinterpret_cast<float4*>(g_agg2)[w * 32 + lane] = acc;
}

// ---------------- 8) GEMM2: out = agg2 @ W2 + b2  [50000 x 128 x 128], col-halved ----------------
__global__ void k_gemm2(const float* __restrict__ W2, const float* __restrict__ b2,
                        float* __restrict__ out) {
    __shared__ float Ws[HID * 64];    // 32 KB, this block's 64-column half
    __shared__ float As[32 * HID];    // 16 KB (total 48 KB static)
    int half = blockIdx.x & 1;
    for (int idx = threadIdx.x; idx < HID * 64; idx += 256) {
        int k = idx >> 6, c = idx & 63;
        Ws[idx] = W2[k * HID + half * 64 + c];
    }
    int tcol = (threadIdx.x & 15) * 4;   // 0..60 within the half
    int trow = (threadIdx.x >> 4) * 2;   // 0..30
    float bv[4];
#pragma unroll
    for (int j = 0; j < 4; j++) bv[j] = __ldg(&b2[half * 64 + tcol + j]);

    const int NT = (NN + 31) / 32;       // 1563
    for (int t = blockIdx.x >> 1; t < NT; t += (gridDim.x >> 1)) {
        int row0 = t * 32;
        __syncthreads();
        for (int idx = threadIdx.x; idx < 32 * HID; idx += 256) {
            int gr = row0 + (idx >> 7);
            As[idx] = (gr < NN) ? g_agg2[gr * HID + (idx & 127)] : 0.f;
        }
        __syncthreads();

        float acc[2][4];
#pragma unroll
        for (int r = 0; r < 2; r++)
#pragma unroll
            for (int j = 0; j < 4; j++) acc[r][j] = bv[j];

#pragma unroll 8
        for (int k = 0; k < HID; k++) {
            float4 w4 = *reinterpret_cast<const float4*>(&Ws[k * 64 + tcol]);
            float a0 = As[trow * HID + k];
            float a1 = As[(trow + 1) * HID + k];
            acc[0][0] += a0 * w4.x; acc[0][1] += a0 * w4.y;
            acc[0][2] += a0 * w4.z; acc[0][3] += a0 * w4.w;
            acc[1][0] += a1 * w4.x; acc[1][1] += a1 * w4.y;
            acc[1][2] += a1 * w4.z; acc[1][3] += a1 * w4.w;
        }
#pragma unroll
        for (int r = 0; r < 2; r++) {
            int gr = row0 + trow + r;
            if (gr < NN) {
                float4 o;
                o.x = acc[r][0]; o.y = acc[r][1]; o.z = acc[r][2]; o.w = acc[r][3];
                *reinterpret_cast<float4*>(&out[gr * HID + half * 64 + tcol]) = o;
            }
        }
    }
}

// ---------------- host launcher ----------------
extern "C" void kernel_launch(void* const* d_in, const int* in_sizes, int n_in,
                              void* d_out, int out_size) {
    // metadata order: x(int32), edge_index(int32 2xE), emb, W1, b1, W2, b2
    // NOTE: JAX x64 is disabled in the reference environment, so the declared
    // int64 tensors are materialized as int32 on device.
    const int*   ei  = (const int*)d_in[1];
    const float* emb = (const float*)d_in[2];
    const float* W1  = (const float*)d_in[3];
    const float* b1  = (const float*)d_in[4];
    const float* W2  = (const float*)d_in[5];
    const float* b2  = (const float*)d_in[6];
    float* out = (float*)d_out;

    k_init      <<<(NN + 255) / 256, 256>>>();
    k_deg       <<<ER / 256, 256>>>(ei);
    k_dinv_alloc<<<(NN + 255) / 256, 256>>>();
    k_scatter   <<<ER / 256, 256>>>(ei);
    k_agg_emb   <<<(NN * 32) / 256, 256>>>(emb);
    k_gemm1     <<<592, 256>>>(W1, b1);
    k_agg_h1    <<<(NN * 32) / 256, 256>>>();
    k_gemm2     <<<592, 256>>>(W2, b2, out);
}

// round 3
// speedup vs baseline: 1.0313x; 1.0313x over previous
#include <cuda_runtime.h>
#include <cuda_fp16.h>

#define NN  50000
#define ER  1600000
#define EMB 32
#define HID 128

typedef unsigned long long u64;
struct u64x2 { u64 lo, hi; };

// ---- packed f32x2 helpers (sm_103a FFMA2 path, PTX-only) ----
__device__ __forceinline__ u64 dup2(float a) {
    u64 r; asm("mov.b64 %0, {%1, %1};" : "=l"(r) : "f"(a)); return r;
}
__device__ __forceinline__ u64 packf2(float a, float b) {
    u64 r; asm("mov.b64 %0, {%1, %2};" : "=l"(r) : "f"(a), "f"(b)); return r;
}
__device__ __forceinline__ void ffma2(u64& d, u64 a, u64 b) {
    asm("fma.rn.f32x2 %0, %1, %2, %0;" : "+l"(d) : "l"(a), "l"(b));
}
__device__ __forceinline__ float2 unpackf2(u64 v) {
    float2 r; asm("mov.b64 {%0, %1}, %2;" : "=f"(r.x), "=f"(r.y) : "l"(v)); return r;
}

// ---------------- device scratch (static, no cudaMalloc) ----------------
__device__ int    g_deg[NN];
__device__ float  g_dinv[NN];
__device__ int    g_rowstart[NN];
__device__ int    g_cursor[NN];
__device__ int    g_col[ER];
__device__ int    g_total;
__device__ float  g_aggemb[NN * EMB];    //  6.4 MB
__device__ __half g_h1h[NN * HID];       // 12.8 MB (fp16 hidden)
__device__ float  g_agg2[NN * HID];      // 25.6 MB

// ---------------- 1) init ----------------
__global__ void k_init() {
    int i = blockIdx.x * 256 + threadIdx.x;
    if (i < NN) g_deg[i] = 1;
    if (i == 0) g_total = 0;
}

// ---------------- 2) degree histogram over dst ----------------
__global__ void k_deg(const int* __restrict__ ei) {
    int e = blockIdx.x * 256 + threadIdx.x;
    if (e < ER) atomicAdd(&g_deg[ei[ER + e]], 1);
}

// ---------------- 3) dinv + CSR row allocation (warp-aggregated bump) ----------------
__global__ void k_dinv_alloc() {
    int i    = blockIdx.x * 256 + threadIdx.x;
    int lane = threadIdx.x & 31;
    int cnt  = 0;
    if (i < NN) {
        int d = g_deg[i];
        g_dinv[i] = rsqrtf((float)d);
        cnt = d - 1;
    }
    int incl = cnt;
#pragma unroll
    for (int off = 1; off < 32; off <<= 1) {
        int t = __shfl_up_sync(0xffffffffu, incl, off);
        if (lane >= off) incl += t;
    }
    int total = __shfl_sync(0xffffffffu, incl, 31);
    int base  = 0;
    if (lane == 31) base = atomicAdd(&g_total, total);
    base = __shfl_sync(0xffffffffu, base, 31);
    if (i < NN) {
        int start = base + incl - cnt;
        g_rowstart[i] = start;
        g_cursor[i]   = start;
    }
}

// ---------------- 4) scatter edges into CSR buckets ----------------
__global__ void k_scatter(const int* __restrict__ ei) {
    int e = blockIdx.x * 256 + threadIdx.x;
    if (e < ER) {
        int s = ei[e];
        int d = ei[ER + e];
        int pos = atomicAdd(&g_cursor[d], 1);
        g_col[pos] = s;
    }
}

// ---------------- 5) aggregate embeddings (32-dim, warp per node) ----------------
__global__ void k_agg_emb(const float* __restrict__ emb) {
    int w    = (blockIdx.x * 256 + threadIdx.x) >> 5;
    int lane = threadIdx.x & 31;
    if (w >= NN) return;
    float di  = g_dinv[w];
    float acc = emb[w * EMB + lane] * di * di;
    int start = g_rowstart[w];
    int cnt   = g_deg[w] - 1;
    for (int e = 0; e < cnt; e++) {
        int   s  = g_col[start + e];
        float ns = g_dinv[s] * di;
        acc += emb[s * EMB + lane] * ns;
    }
    g_aggemb[w * EMB + lane] = acc;
}

// ---------------- 6) GEMM1: h1 = relu(aggemb @ W1 + b1) -> fp16 ----------------
__global__ void k_gemm1(const float* __restrict__ W1, const float* __restrict__ b1) {
    __shared__ float Ws[EMB * HID];   // 16 KB
    __shared__ float As[16 * EMB];    //  2 KB
    for (int idx = threadIdx.x; idx < EMB * HID; idx += 256) Ws[idx] = W1[idx];

    int tcol = (threadIdx.x & 31) * 4;        // 0..124
    int trow = (threadIdx.x >> 5) * 2;        // 0..14
    u64 bias01 = packf2(__ldg(&b1[tcol]),     __ldg(&b1[tcol + 1]));
    u64 bias23 = packf2(__ldg(&b1[tcol + 2]), __ldg(&b1[tcol + 3]));

    const int NT = NN / 16;                   // 3125 exact
    for (int t = blockIdx.x; t < NT; t += gridDim.x) {
        int row0 = t * 16;
        __syncthreads();
        for (int idx = threadIdx.x; idx < 16 * EMB / 4; idx += 256)
            ((float4*)As)[idx] = ((const float4*)g_aggemb)[row0 * (EMB / 4) + idx];
        __syncthreads();

        u64 acc[2][2] = {{bias01, bias23}, {bias01, bias23}};
#pragma unroll
        for (int k = 0; k < EMB; k++) {
            u64x2 w = *reinterpret_cast<const u64x2*>(&Ws[k * HID + tcol]);
            u64 a0 = dup2(As[trow * EMB + k]);
            u64 a1 = dup2(As[(trow + 1) * EMB + k]);
            ffma2(acc[0][0], a0, w.lo); ffma2(acc[0][1], a0, w.hi);
            ffma2(acc[1][0], a1, w.lo); ffma2(acc[1][1], a1, w.hi);
        }
#pragma unroll
        for (int r = 0; r < 2; r++) {
            float2 p01 = unpackf2(acc[r][0]);
            float2 p23 = unpackf2(acc[r][1]);
            __half2 h01 = __floats2half2_rn(fmaxf(p01.x, 0.f), fmaxf(p01.y, 0.f));
            __half2 h23 = __floats2half2_rn(fmaxf(p23.x, 0.f), fmaxf(p23.y, 0.f));
            uint2 st;
            st.x = *reinterpret_cast<unsigned*>(&h01);
            st.y = *reinterpret_cast<unsigned*>(&h23);
            *reinterpret_cast<uint2*>(&g_h1h[(row0 + trow + r) * HID + tcol]) = st;
        }
    }
}

// ---------------- 7) aggregate h1 (fp16 gather, fp32 accumulate, warp per node) ----------------
__global__ void k_agg_h1() {
    int w    = (blockIdx.x * 256 + threadIdx.x) >> 5;
    int lane = threadIdx.x & 31;
    if (w >= NN) return;
    float di = g_dinv[w];
    const uint2* hv = reinterpret_cast<const uint2*>(g_h1h);  // 4 halves / uint2
    uint2 v = hv[w * 32 + lane];
    float2 vl = __half22float2(*reinterpret_cast<__half2*>(&v.x));
    float2 vh = __half22float2(*reinterpret_cast<__half2*>(&v.y));
    float  sw = di * di;
    float4 acc = make_float4(vl.x * sw, vl.y * sw, vh.x * sw, vh.y * sw);
    int start = g_rowstart[w];
    int cnt   = g_deg[w] - 1;
    for (int e = 0; e < cnt; e++) {
        int   s  = g_col[start + e];
        float ns = g_dinv[s] * di;
        uint2 u  = hv[s * 32 + lane];
        float2 ul = __half22float2(*reinterpret_cast<__half2*>(&u.x));
        float2 uh = __half22float2(*reinterpret_cast<__half2*>(&u.y));
        acc.x += ul.x * ns; acc.y += ul.y * ns;
        acc.z += uh.x * ns; acc.w += uh.y * ns;
    }
    reinterpret_cast<float4*>(g_agg2)[w * 32 + lane] = acc;
}

// ---------------- 8) GEMM2: out = agg2 @ W2 + b2, col-halved, FFMA2 ----------------
__global__ void k_gemm2(const float* __restrict__ W2, const float* __restrict__ b2,
                        float* __restrict__ out) {
    __shared__ float Ws[HID * 64];    // 32 KB
    __shared__ float As[32 * HID];    // 16 KB (48 KB total)
    int half = blockIdx.x & 1;
    for (int idx = threadIdx.x; idx < HID * 64; idx += 256) {
        int k = idx >> 6, c = idx & 63;
        Ws[idx] = W2[k * HID + half * 64 + c];
    }
    int tcol = (threadIdx.x & 15) * 4;   // 0..60 within the half
    int trow = (threadIdx.x >> 4) * 2;   // 0..30
    u64 bias01 = packf2(__ldg(&b2[half * 64 + tcol]),     __ldg(&b2[half * 64 + tcol + 1]));
    u64 bias23 = packf2(__ldg(&b2[half * 64 + tcol + 2]), __ldg(&b2[half * 64 + tcol + 3]));

    const int NT = (NN + 31) / 32;       // 1563
    for (int t = blockIdx.x >> 1; t < NT; t += (gridDim.x >> 1)) {
        int row0 = t * 32;
        __syncthreads();
        for (int idx = threadIdx.x; idx < 32 * HID / 4; idx += 256) {
            int gr = row0 + (idx >> 5);
            ((float4*)As)[idx] = (gr < NN)
                ? ((const float4*)g_agg2)[gr * 32 + (idx & 31)]
                : make_float4(0.f, 0.f, 0.f, 0.f);
        }
        __syncthreads();

        u64 acc[2][2] = {{bias01, bias23}, {bias01, bias23}};
#pragma unroll 8
        for (int k = 0; k < HID; k++) {
            u64x2 w = *reinterpret_cast<const u64x2*>(&Ws[k * 64 + tcol]);
            u64 a0 = dup2(As[trow * HID + k]);
            u64 a1 = dup2(As[(trow + 1) * HID + k]);
            ffma2(acc[0][0], a0, w.lo); ffma2(acc[0][1], a0, w.hi);
            ffma2(acc[1][0], a1, w.lo); ffma2(acc[1][1], a1, w.hi);
        }
#pragma unroll
        for (int r = 0; r < 2; r++) {
            int gr = row0 + trow + r;
            if (gr < NN) {
                float2 p01 = unpackf2(acc[r][0]);
                float2 p23 = unpackf2(acc[r][1]);
                float4 o = make_float4(p01.x, p01.y, p23.x, p23.y);
                *reinterpret_cast<float4*>(&out[gr * HID + half * 64 + tcol]) = o;
            }
        }
    }
}

// ---------------- host launcher ----------------
extern "C" void kernel_launch(void* const* d_in, const int* in_sizes, int n_in,
                              void* d_out, int out_size) {
    const int*   ei  = (const int*)d_in[1];
    const float* emb = (const float*)d_in[2];
    const float* W1  = (const float*)d_in[3];
    const float* b1  = (const float*)d_in[4];
    const float* W2  = (const float*)d_in[5];
    const float* b2  = (const float*)d_in[6];
    float* out = (float*)d_out;

    k_init      <<<(NN + 255) / 256, 256>>>();
    k_deg       <<<ER / 256, 256>>>(ei);
    k_dinv_alloc<<<(NN + 255) / 256, 256>>>();
    k_scatter   <<<ER / 256, 256>>>(ei);
    k_agg_emb   <<<(NN * 32) / 256, 256>>>(emb);
    k_gemm1     <<<592, 256>>>(W1, b1);
    k_agg_h1    <<<(NN * 32) / 256, 256>>>();
    k_gemm2     <<<592, 256>>>(W2, b2, out);
}